// round 17
// baseline (speedup 1.0000x reference)
#include <cuda_runtime.h>
#include <math.h>

typedef unsigned long long ull;

#define BB 64
#define TT 512
#define II 256
#define HH 512
#define CC 40
#define G4 2048     // 4*H
#define NB 128      // persistent blocks, all co-resident (<=148 SMs, 1 block/SM)

// -------------------- device scratch --------------------
__device__ __align__(256) float g_xg [(size_t)BB * TT * G4];   // [m=b*T+t][n]
__device__ __align__(256) float g_xgT[(size_t)TT * G4 * BB];   // [t][n][b]
__device__ __align__(256) float g_hbuf[2 * HH * BB];           // [parity][unit][b]
__device__ volatile unsigned g_uflag[NB * 8 * 32];             // per-(block,unit-warp) flag, one 128B line each

// -------------------- f32x2 helpers --------------------
__device__ __forceinline__ ull pack2(float x, float y) {
    ull r; asm("mov.b64 %0, {%1, %2};" : "=l"(r) : "f"(x), "f"(y)); return r;
}
__device__ __forceinline__ void unpack2(ull v, float& x, float& y) {
    asm("mov.b64 {%0, %1}, %2;" : "=f"(x), "=f"(y) : "l"(v));
}
__device__ __forceinline__ ull ffma2(ull a, ull b, ull c) {
    ull d; asm("fma.rn.f32x2 %0, %1, %2, %3;" : "=l"(d) : "l"(a), "l"(b), "l"(c)); return d;
}
// 32B L2 (.cg) load as four ulls
__device__ __forceinline__ void ldcg32(const void* p, ull& a, ull& b, ull& c, ull& d) {
    asm volatile("ld.global.cg.v2.u64 {%0, %1}, [%2];" : "=l"(a), "=l"(b) : "l"(p));
    asm volatile("ld.global.cg.v2.u64 {%0, %1}, [%2];" : "=l"(c), "=l"(d) : "l"((const char*)p + 16));
}

// fast activations (MUFU-based; err ~1e-6, well within 1e-3 budget)
__device__ __forceinline__ float fsig(float x) {
    return __fdividef(1.f, 1.f + __expf(-x));
}
__device__ __forceinline__ float ftanh(float x) {
    float ax = fabsf(x);
    float e  = __expf(-2.f * ax);
    float r  = __fdividef(1.f - e, 1.f + e);
    return x < 0.f ? -r : r;
}

// -------------------- kernel 1: xg = x @ W_ih^T + (b_ih + b_hh), f32x2 --------------------
__global__ void __launch_bounds__(256) gemm_xg(const float* __restrict__ x,
                                               const float* __restrict__ Wih,
                                               const float* __restrict__ bih,
                                               const float* __restrict__ bhh) {
    __shared__ __align__(16) float As[16][132];   // [k][m]
    __shared__ __align__(16) float Bs[16][132];   // [k][n] permuted
    const int tid  = threadIdx.x;
    const int m0   = blockIdx.y * 128;
    const int n0   = blockIdx.x * 128;
    const int tx   = tid & 15;
    const int ty   = tid >> 4;
    const int lrow = tid >> 2;
    const int lkq  = (tid & 3) << 2;
    char* BsB = (char*)Bs;

    ull acc2[8][4];
#pragma unroll
    for (int i = 0; i < 8; i++)
#pragma unroll
        for (int j = 0; j < 4; j++) acc2[i][j] = 0ull;

    const unsigned posA = ((unsigned)(tx & 1)) * 256u + ((unsigned)(tx >> 1)) * 16u;

    for (int k0 = 0; k0 < II; k0 += 16) {
        float4 a0 = *(const float4*)(x   + (size_t)(m0 + lrow)      * II + k0 + lkq);
        float4 a1 = *(const float4*)(x   + (size_t)(m0 + lrow + 64) * II + k0 + lkq);
        float4 b0 = *(const float4*)(Wih + (size_t)(n0 + lrow)      * II + k0 + lkq);
        float4 b1 = *(const float4*)(Wih + (size_t)(n0 + lrow + 64) * II + k0 + lkq);
        __syncthreads();
        As[lkq+0][lrow]    = a0.x; As[lkq+1][lrow]    = a0.y;
        As[lkq+2][lrow]    = a0.z; As[lkq+3][lrow]    = a0.w;
        As[lkq+0][lrow+64] = a1.x; As[lkq+1][lrow+64] = a1.y;
        As[lkq+2][lrow+64] = a1.z; As[lkq+3][lrow+64] = a1.w;
        {
            int c0 = lrow, c1 = lrow + 64;
            unsigned o0 = (unsigned)(((c0 >> 2) & 3) << 7) + (unsigned)((c0 >> 4) << 4) + (unsigned)((c0 & 3) << 2);
            unsigned o1 = (unsigned)(((c1 >> 2) & 3) << 7) + (unsigned)((c1 >> 4) << 4) + (unsigned)((c1 & 3) << 2);
            *(float*)(BsB + (lkq+0)*528 + o0) = b0.x;
            *(float*)(BsB + (lkq+1)*528 + o0) = b0.y;
            *(float*)(BsB + (lkq+2)*528 + o0) = b0.z;
            *(float*)(BsB + (lkq+3)*528 + o0) = b0.w;
            *(float*)(BsB + (lkq+0)*528 + o1) = b1.x;
            *(float*)(BsB + (lkq+1)*528 + o1) = b1.y;
            *(float*)(BsB + (lkq+2)*528 + o1) = b1.z;
            *(float*)(BsB + (lkq+3)*528 + o1) = b1.w;
        }
        __syncthreads();
#pragma unroll
        for (int k = 0; k < 16; k++) {
            float a[8];
            *(float4*)(a)     = *(float4*)&As[k][ty * 8];
            *(float4*)(a + 4) = *(float4*)&As[k][ty * 8 + 4];
            ulonglong2 bA = *(ulonglong2*)(BsB + k*528 + posA);
            ulonglong2 bB = *(ulonglong2*)(BsB + k*528 + posA + 128);
            ull b2[4] = {bA.x, bA.y, bB.x, bB.y};
#pragma unroll
            for (int i = 0; i < 8; i++) {
                ull a2 = pack2(a[i], a[i]);
                acc2[i][0] = ffma2(a2, b2[0], acc2[i][0]);
                acc2[i][1] = ffma2(a2, b2[1], acc2[i][1]);
                acc2[i][2] = ffma2(a2, b2[2], acc2[i][2]);
                acc2[i][3] = ffma2(a2, b2[3], acc2[i][3]);
            }
        }
    }

    float bias[8];
#pragma unroll
    for (int j = 0; j < 8; j++) {
        int n = n0 + tx * 8 + j;
        bias[j] = bih[n] + bhh[n];
    }
#pragma unroll
    for (int i = 0; i < 8; i++) {
        size_t m = (size_t)(m0 + ty * 8 + i);
        float o[8];
#pragma unroll
        for (int j = 0; j < 4; j++) unpack2(acc2[i][j], o[2*j], o[2*j+1]);
        float4 v0, v1;
        v0.x = o[0] + bias[0]; v0.y = o[1] + bias[1];
        v0.z = o[2] + bias[2]; v0.w = o[3] + bias[3];
        v1.x = o[4] + bias[4]; v1.y = o[5] + bias[5];
        v1.z = o[6] + bias[6]; v1.w = o[7] + bias[7];
        *(float4*)(g_xg + m * G4 + n0 + tx * 8)     = v0;
        *(float4*)(g_xg + m * G4 + n0 + tx * 8 + 4) = v1;
    }
}

// -------------------- kernel 2: transpose xg[b*T+t][n] -> xgT[t][n][b] --------------------
__global__ void __launch_bounds__(256) transpose_xg() {
    __shared__ float tile[64][65];
    const int t   = blockIdx.x;
    const int n0  = blockIdx.y << 6;
    const int tid = threadIdx.x;
    const int a   = tid & 63;
    const int r   = tid >> 6;
    for (int b = r; b < 64; b += 4)
        tile[a][b] = g_xg[(size_t)(b * TT + t) * G4 + n0 + a];
    __syncthreads();
    for (int n = r; n < 64; n += 4)
        g_xgT[((size_t)t * G4 + n0 + n) * BB + a] = tile[n][a];
}

// -------------------- noop: capture-window alignment for ncu --------------------
__global__ void noop_pad() {}

// -------------------- kernel 3: persistent LSTM recurrence --------------------
// R15 tiling (8 units x 32 batches, 512 threads) + per-unit-warp flag publication:
//  * Gate role (tid<256): warp uu == unit uu's 32 cells. After elementwise, each
//    gate warp stores its h row, __syncwarp + fence, lane0 publishes its OWN
//    padded flag g_uflag[bx*8+uu]. NO second __syncthreads.
//  * Compute role (all 16 warps): warp kg polls its 4 producer blocks x 8 units
//    = 32 padded flags in ONE 32-lane poll instr, then FMAs k-split
//    [32kg,32kg+32) from L2. Warps 8..15 flow straight from sync#1 to t+1's
//    poll, overlapping the gate phase chip-wide.
//  * red double-buffered by step parity (needed once sync#2 is gone).
// smem: Wsm float [512][32] 64KB | red[2][16][32][32] 128KB = 192KB
#define SMEM_LSTM (65536 + 131072)
__global__ void __launch_bounds__(512, 1) lstm_rec(const float* __restrict__ Whh) {
    extern __shared__ char smc[];
    float* Wsm  = (float*)smc;               // [512][32]  w[k][lr]
    float* red  = (float*)(smc + 65536);     // [2][16][32][32]
    ull*   red2 = (ull*)red;

    const int tid  = threadIdx.x;
    const int bx   = blockIdx.x;
    const int ublk = bx >> 1;                // unit group (8 units)
    const int bh   = bx & 1;                 // batch half
    const unsigned S = g_uflag[(bx << 3) * 32];  // epoch base (all flags consistent)

    // Load W_hh slice: Wsm[k*32 + lr] = Whh[row(lr)][k], lr = g*8+u
    for (int idx = tid; idx < 32 * 512; idx += 512) {
        int k   = idx >> 5;
        int lr  = idx & 31;
        int row = ((lr >> 3) << 9) + (ublk << 3) + (lr & 7);
        Wsm[(k << 5) + lr] = Whh[(size_t)row * HH + k];
    }

    // gate-role mapping (threads 0..255): warp uu = unit, lane = batch
    const int uu  = tid >> 5;        // 0..7 (valid for tid<256)
    const int b32 = tid & 31;        // batch within half
    const int ug  = (ublk << 3) + uu;

    if (tid < 256) g_hbuf[ug * 64 + (bh << 5) + b32] = 0.f;   // h0 = 0 (parity 0)
    float c = 0.f;
    __syncthreads();
    if (tid < 256 && (tid & 31) == 0) {
        __threadfence();
        g_uflag[((bx << 3) + uu) * 32] = S + 1;   // h_0 ready (per unit warp)
    }

    // compute-role mapping
    const int kg   = tid >> 5;      // warp id 0..15 = k-split, krange 32
    const int lane = tid & 31;
    const int rq   = lane >> 2;     // 0..7 -> rows 4rq..4rq+3 (of 32 local rows)
    const int bq   = lane & 3;      // 0..3 -> batches 8bq..8bq+7 (of 32)
    // producer flags: blocks ublk' = 4kg + (lane>>3) (same bh), unit lane&7
    const int prod = ((((((kg << 2) + (lane >> 3)) << 1) + bh) << 3) + (lane & 7)) * 32;
    const float* wk0 = Wsm + (kg << 10) + (rq << 2);         // k=32kg, rows 4rq..
    const int rbase = (kg << 9) + (rq << 6) + (bq << 2);     // red2 ull base within buffer
    const int krow0 = kg << 5;

    for (int t = 0; t < TT; t++) {
        const int p = t & 1;

        // prefetch xg for this step (independent of h; threads 0..255)
        float xgv[4];
        if (tid < 256) {
#pragma unroll
            for (int g = 0; g < 4; g++)
                xgv[g] = __ldg(&g_xgT[((size_t)t * G4 + (g << 9) + ug) * 64 + (bh << 5) + b32]);
        }

        // wait for this warp's 32 producer unit-flags (one poll instr per retry)
        {
            const unsigned want = S + 1 + (unsigned)t;
            while ((int)(g_uflag[prod] - want) < 0) { }
            __syncwarp();
            __threadfence();   // acquire: order h reads after flag observation
        }

        ull acc[4][4];
#pragma unroll
        for (int j = 0; j < 4; j++)
#pragma unroll
            for (int u = 0; u < 4; u++) acc[j][u] = 0ull;

        const char* hk = (const char*)(g_hbuf + (size_t)p * HH * 64)
                       + (krow0 << 8) + (bh << 7) + (bq << 5);   // k*256B + half*128B + bq*32B
        const float* wk = wk0;
#pragma unroll 4
        for (int k = 0; k < 32; k++) {
            ull hx, hy, hz, hw;
            ldcg32(hk, hx, hy, hz, hw);                  // 8 batches of h[k] (this half)
            float4 wv = *(const float4*)wk;              // rows 4rq..4rq+3 at this k
            hk += 256; wk += 32;
            ull w0 = pack2(wv.x, wv.x);
            ull w1 = pack2(wv.y, wv.y);
            ull w2 = pack2(wv.z, wv.z);
            ull w3 = pack2(wv.w, wv.w);
            acc[0][0] = ffma2(w0, hx, acc[0][0]);
            acc[0][1] = ffma2(w0, hy, acc[0][1]);
            acc[0][2] = ffma2(w0, hz, acc[0][2]);
            acc[0][3] = ffma2(w0, hw, acc[0][3]);
            acc[1][0] = ffma2(w1, hx, acc[1][0]);
            acc[1][1] = ffma2(w1, hy, acc[1][1]);
            acc[1][2] = ffma2(w1, hz, acc[1][2]);
            acc[1][3] = ffma2(w1, hw, acc[1][3]);
            acc[2][0] = ffma2(w2, hx, acc[2][0]);
            acc[2][1] = ffma2(w2, hy, acc[2][1]);
            acc[2][2] = ffma2(w2, hz, acc[2][2]);
            acc[2][3] = ffma2(w2, hw, acc[2][3]);
            acc[3][0] = ffma2(w3, hx, acc[3][0]);
            acc[3][1] = ffma2(w3, hy, acc[3][1]);
            acc[3][2] = ffma2(w3, hz, acc[3][2]);
            acc[3][3] = ffma2(w3, hw, acc[3][3]);
        }

        // red[p][kg][lr][b32]: partials for rows 4rq..4rq+3, batches 8bq..8bq+7
        {
            ull* rb = red2 + (p << 13) + rbase;
#pragma unroll
            for (int j = 0; j < 4; j++) {
                *(ulonglong2*)(rb + j * 16)     = make_ulonglong2(acc[j][0], acc[j][1]);
                *(ulonglong2*)(rb + j * 16 + 2) = make_ulonglong2(acc[j][2], acc[j][3]);
            }
        }
        __syncthreads();   // sync#1: red[p] complete; compute-only warps run ahead

        // elementwise (gate warps only): combine 16 partials + xg, gates, update
        if (tid < 256) {
            float s[4];
#pragma unroll
            for (int g = 0; g < 4; g++) {
                int lr = (g << 3) + uu;
                const float* rp = red + (p << 14) + (lr << 5) + b32;
                float v = 0.f;
#pragma unroll
                for (int k2 = 0; k2 < 16; k2++)
                    v += rp[k2 << 10];
                s[g] = v + xgv[g];
            }
            float ig = fsig(s[0]);
            float fg = fsig(s[1]);
            float gg = ftanh(s[2]);
            float og = fsig(s[3]);
            c = fmaf(fg, c, ig * gg);
            float h = og * ftanh(c);
            g_hbuf[((p ^ 1) * HH + ug) * 64 + (bh << 5) + b32] = h;
            __syncwarp();
            __threadfence();
            if ((tid & 31) == 0)
                g_uflag[((bx << 3) + uu) * 32] = S + 2 + (unsigned)t;   // per-unit publish
        }
    }
    // h_last = h_512 in parity 0
}

// -------------------- kernel 4: out = h_last @ W_fc^T + b_fc --------------------
__global__ void __launch_bounds__(256) fc_out(const float* __restrict__ Wfc,
                                              const float* __restrict__ bfc,
                                              float* __restrict__ out) {
    __shared__ float hs[HH];
    const int b = blockIdx.x;
    for (int u = threadIdx.x; u < HH; u += 256) hs[u] = g_hbuf[u * 64 + b];
    __syncthreads();
    const int w = threadIdx.x >> 5, lane = threadIdx.x & 31;
    for (int cc = w; cc < CC; cc += 8) {
        float s = 0.f;
        for (int u = lane; u < HH; u += 32) s = fmaf(hs[u], Wfc[cc * HH + u], s);
#pragma unroll
        for (int o = 16; o; o >>= 1) s += __shfl_xor_sync(0xffffffffu, s, o);
        if (lane == 0) out[b * CC + cc] = s + bfc[cc];
    }
}

// -------------------- launch --------------------
extern "C" void kernel_launch(void* const* d_in, const int* in_sizes, int n_in,
                              void* d_out, int out_size) {
    (void)in_sizes; (void)n_in; (void)out_size;
    const float* x   = (const float*)d_in[0];
    const float* Wih = (const float*)d_in[1];
    const float* Whh = (const float*)d_in[2];
    const float* bih = (const float*)d_in[3];
    const float* bhh = (const float*)d_in[4];
    const float* Wfc = (const float*)d_in[5];
    const float* bfc = (const float*)d_in[6];
    float* out = (float*)d_out;

    gemm_xg<<<dim3(G4 / 128, (BB * TT) / 128), 256>>>(x, Wih, bih, bhh);
    transpose_xg<<<dim3(TT, G4 / 64), 256>>>();
    noop_pad<<<1, 32>>>();   // aligns ncu capture index onto lstm_rec

    cudaFuncSetAttribute(lstm_rec, cudaFuncAttributeMaxDynamicSharedMemorySize, SMEM_LSTM);
    lstm_rec<<<NB, 512, SMEM_LSTM>>>(Whh);

    fc_out<<<BB, 256>>>(Wfc, bfc, out);
}